// round 4
// baseline (speedup 1.0000x reference)
#include <cuda_runtime.h>

#define B_   4
#define S_   2048
#define EMB_ 1024
#define H_   16
#define D_   64
#define MROWS (B_ * S_)   // 8192

#define QS_STRIDE 65
#define KS_STRIDE 65
#define VS_STRIDE 64
#define ATTN_SMEM_FLOATS (64 * QS_STRIDE + 64 * KS_STRIDE + 64 * VS_STRIDE)
#define ATTN_SMEM_BYTES  (ATTN_SMEM_FLOATS * 4)

// Scratch (device-global arrays: allocation-free per harness rules)
__device__ float g_q[MROWS * EMB_];
__device__ float g_k[MROWS * EMB_];
__device__ float g_v[MROWS * EMB_];
__device__ float g_attn[MROWS * EMB_];

// ---------------------------------------------------------------------------
// SGEMM: C[M,1024] = A[M,1024] @ W[1024,1024] + bias[1024]
// 128x128 block tile, BK=16, 256 threads, 8x8 register micro-tile.
// ---------------------------------------------------------------------------
__global__ void __launch_bounds__(256) gemm_bias_kernel(
    const float* __restrict__ A,
    const float* __restrict__ W,
    const float* __restrict__ bias,
    float* __restrict__ C)
{
    __shared__ float As[16][128];   // transposed: As[k][m]
    __shared__ float Bs[16][128];

    const int tid = threadIdx.x;
    const int m0  = blockIdx.y * 128;
    const int n0  = blockIdx.x * 128;
    const int tm  = (tid >> 4) * 8;
    const int tn  = (tid & 15) * 8;

    float acc[8][8];
    #pragma unroll
    for (int i = 0; i < 8; ++i)
        #pragma unroll
        for (int j = 0; j < 8; ++j) acc[i][j] = 0.f;

    for (int kb = 0; kb < 1024; kb += 16) {
        #pragma unroll
        for (int t = 0; t < 2; ++t) {
            int f   = tid + t * 256;
            int ar  = f >> 2;       // 0..127
            int ac4 = f & 3;        // 0..3
            float4 av = *(const float4*)(A + (size_t)(m0 + ar) * 1024 + kb + ac4 * 4);
            As[ac4 * 4 + 0][ar] = av.x;
            As[ac4 * 4 + 1][ar] = av.y;
            As[ac4 * 4 + 2][ar] = av.z;
            As[ac4 * 4 + 3][ar] = av.w;
        }
        #pragma unroll
        for (int t = 0; t < 2; ++t) {
            int f   = tid + t * 256;
            int br  = f >> 5;       // 0..15
            int bc4 = f & 31;       // 0..31
            *(float4*)&Bs[br][bc4 * 4] =
                *(const float4*)(W + (size_t)(kb + br) * 1024 + n0 + bc4 * 4);
        }
        __syncthreads();

        #pragma unroll
        for (int kk = 0; kk < 16; ++kk) {
            float a[8], b[8];
            *(float4*)&a[0] = *(float4*)&As[kk][tm];
            *(float4*)&a[4] = *(float4*)&As[kk][tm + 4];
            *(float4*)&b[0] = *(float4*)&Bs[kk][tn];
            *(float4*)&b[4] = *(float4*)&Bs[kk][tn + 4];
            #pragma unroll
            for (int i = 0; i < 8; ++i)
                #pragma unroll
                for (int j = 0; j < 8; ++j)
                    acc[i][j] = fmaf(a[i], b[j], acc[i][j]);
        }
        __syncthreads();
    }

    float bv[8];
    *(float4*)&bv[0] = *(const float4*)(bias + n0 + tn);
    *(float4*)&bv[4] = *(const float4*)(bias + n0 + tn + 4);

    #pragma unroll
    for (int i = 0; i < 8; ++i) {
        float4 o0 = { acc[i][0] + bv[0], acc[i][1] + bv[1],
                      acc[i][2] + bv[2], acc[i][3] + bv[3] };
        float4 o1 = { acc[i][4] + bv[4], acc[i][5] + bv[5],
                      acc[i][6] + bv[6], acc[i][7] + bv[7] };
        float* cp = C + (size_t)(m0 + tm + i) * 1024 + n0 + tn;
        *(float4*)(cp)     = o0;
        *(float4*)(cp + 4) = o1;
    }
}

// ---------------------------------------------------------------------------
// Flash attention: one block per (b, h, 64-row q-tile).
// Q/K/V layout: (B*S, EMB) with head h at column offset h*64.
// Online softmax; P reuses K's smem buffer. Dynamic smem (49,664 B).
// Mask is 4-byte 0/1 per (b, key_position).
// ---------------------------------------------------------------------------
__global__ void __launch_bounds__(256) attn_kernel(const int* __restrict__ mask)
{
    extern __shared__ float smem[];
    float* Qs = smem;                              // [64][65]
    float* Ks = smem + 64 * QS_STRIDE;             // [64][65]; reused as P
    float* Vs = smem + 64 * (QS_STRIDE + KS_STRIDE); // [64][64]

    const int tid = threadIdx.x;
    const int tx  = tid & 15;       // 16 col-groups
    const int ty  = tid >> 4;       // 16 row-groups
    const int bh  = blockIdx.y;
    const int b   = bh >> 4;
    const int h   = bh & 15;
    const int q0  = blockIdx.x << 6;

    // Load Q tile (64 x 64)
    const float* qg = g_q + ((size_t)(b * S_ + q0)) * EMB_ + h * D_;
    #pragma unroll
    for (int it = 0; it < 4; ++it) {
        int r = (tid >> 4) + (it << 4);
        int c = (tid & 15) << 2;
        float4 t = *(const float4*)(qg + (size_t)r * EMB_ + c);
        Qs[r * QS_STRIDE + c + 0] = t.x;
        Qs[r * QS_STRIDE + c + 1] = t.y;
        Qs[r * QS_STRIDE + c + 2] = t.z;
        Qs[r * QS_STRIDE + c + 3] = t.w;
    }

    float O[4][4] = {};
    float m_i[4], l_i[4];
    #pragma unroll
    for (int i = 0; i < 4; ++i) { m_i[i] = -1e30f; l_i[i] = 0.f; }

    __syncthreads();

    const int* mrow = mask + b * S_;

    for (int kt = 0; kt < S_ / 64; ++kt) {
        const int k0 = kt << 6;
        const float* kg = g_k + ((size_t)(b * S_ + k0)) * EMB_ + h * D_;
        const float* vg = g_v + ((size_t)(b * S_ + k0)) * EMB_ + h * D_;

        #pragma unroll
        for (int it = 0; it < 4; ++it) {
            int r = (tid >> 4) + (it << 4);
            int c = (tid & 15) << 2;
            float4 tk = *(const float4*)(kg + (size_t)r * EMB_ + c);
            Ks[r * KS_STRIDE + c + 0] = tk.x;
            Ks[r * KS_STRIDE + c + 1] = tk.y;
            Ks[r * KS_STRIDE + c + 2] = tk.z;
            Ks[r * KS_STRIDE + c + 3] = tk.w;
            float4 tv = *(const float4*)(vg + (size_t)r * EMB_ + c);
            *(float4*)&Vs[r * VS_STRIDE + c] = tv;
        }
        __syncthreads();

        // S = (Q K^T) * scale + mask   (each thread: 4 q-rows x 4 k-cols)
        float S[4][4] = {};
        #pragma unroll 8
        for (int d = 0; d < 64; ++d) {
            float qa[4], kb[4];
            #pragma unroll
            for (int i = 0; i < 4; ++i) qa[i] = Qs[(ty * 4 + i) * QS_STRIDE + d];
            #pragma unroll
            for (int j = 0; j < 4; ++j) kb[j] = Ks[(tx * 4 + j) * KS_STRIDE + d];
            #pragma unroll
            for (int i = 0; i < 4; ++i)
                #pragma unroll
                for (int j = 0; j < 4; ++j)
                    S[i][j] = fmaf(qa[i], kb[j], S[i][j]);
        }

        // Mask: 4-byte 0/1 per key position
        int4 mv = *(const int4*)(mrow + k0 + tx * 4);
        float madd[4] = { mv.x ? 0.f : -1e30f, mv.y ? 0.f : -1e30f,
                          mv.z ? 0.f : -1e30f, mv.w ? 0.f : -1e30f };
        #pragma unroll
        for (int i = 0; i < 4; ++i)
            #pragma unroll
            for (int j = 0; j < 4; ++j)
                S[i][j] = S[i][j] * 0.125f + madd[j];

        // Online softmax (row reductions over 16 lanes sharing a q-row)
        float a_i[4];
        #pragma unroll
        for (int i = 0; i < 4; ++i) {
            float mx = fmaxf(fmaxf(S[i][0], S[i][1]), fmaxf(S[i][2], S[i][3]));
            #pragma unroll
            for (int off = 8; off; off >>= 1)
                mx = fmaxf(mx, __shfl_xor_sync(0xffffffffu, mx, off));
            float mn = fmaxf(m_i[i], mx);
            a_i[i] = __expf(m_i[i] - mn);
            m_i[i] = mn;
            float sum = 0.f;
            #pragma unroll
            for (int j = 0; j < 4; ++j) {
                S[i][j] = __expf(S[i][j] - mn);
                sum += S[i][j];
            }
            #pragma unroll
            for (int off = 8; off; off >>= 1)
                sum += __shfl_xor_sync(0xffffffffu, sum, off);
            l_i[i] = l_i[i] * a_i[i] + sum;
        }

        __syncthreads();            // everyone done reading Ks as K
        // Write P into Ks buffer
        #pragma unroll
        for (int i = 0; i < 4; ++i)
            #pragma unroll
            for (int j = 0; j < 4; ++j)
                Ks[(ty * 4 + i) * KS_STRIDE + tx * 4 + j] = S[i][j];
        __syncthreads();

        // O = O * a + P @ V
        #pragma unroll
        for (int i = 0; i < 4; ++i)
            #pragma unroll
            for (int j = 0; j < 4; ++j)
                O[i][j] *= a_i[i];

        #pragma unroll 8
        for (int kk = 0; kk < 64; ++kk) {
            float pr[4], vr[4];
            #pragma unroll
            for (int i = 0; i < 4; ++i) pr[i] = Ks[(ty * 4 + i) * KS_STRIDE + kk];
            *(float4*)vr = *(const float4*)&Vs[kk * VS_STRIDE + tx * 4];
            #pragma unroll
            for (int i = 0; i < 4; ++i)
                #pragma unroll
                for (int j = 0; j < 4; ++j)
                    O[i][j] = fmaf(pr[i], vr[j], O[i][j]);
        }
        __syncthreads();            // before next tile overwrites Ks/Vs
    }

    // Normalize and write to (B*S, EMB) layout for the output projection
    float* og = g_attn + ((size_t)(b * S_ + q0)) * EMB_ + h * D_;
    #pragma unroll
    for (int i = 0; i < 4; ++i) {
        float inv = 1.0f / l_i[i];
        float4 o = { O[i][0] * inv, O[i][1] * inv, O[i][2] * inv, O[i][3] * inv };
        *(float4*)(og + (size_t)(ty * 4 + i) * EMB_ + tx * 4) = o;
    }
}

// ---------------------------------------------------------------------------
extern "C" void kernel_launch(void* const* d_in, const int* in_sizes, int n_in,
                              void* d_out, int out_size)
{
    const float* query = (const float*)d_in[0];
    const float* key   = (const float*)d_in[1];
    const float* value = (const float*)d_in[2];
    const int*   mask  = (const int*)d_in[3];
    const float* Wq = (const float*)d_in[4];
    const float* bq = (const float*)d_in[5];
    const float* Wk = (const float*)d_in[6];
    const float* bk = (const float*)d_in[7];
    const float* Wv = (const float*)d_in[8];
    const float* bv = (const float*)d_in[9];
    const float* Wo = (const float*)d_in[10];
    const float* bo = (const float*)d_in[11];
    float* out = (float*)d_out;

    float *qp, *kp, *vp, *ap;
    cudaGetSymbolAddress((void**)&qp, g_q);
    cudaGetSymbolAddress((void**)&kp, g_k);
    cudaGetSymbolAddress((void**)&vp, g_v);
    cudaGetSymbolAddress((void**)&ap, g_attn);

    static int smem_set = 0;
    if (!smem_set) {
        cudaFuncSetAttribute(attn_kernel,
                             cudaFuncAttributeMaxDynamicSharedMemorySize,
                             ATTN_SMEM_BYTES);
        smem_set = 1;
    }

    dim3 ggrid(EMB_ / 128, MROWS / 128);   // (8, 64)
    gemm_bias_kernel<<<ggrid, 256>>>(query, Wq, bq, qp);
    gemm_bias_kernel<<<ggrid, 256>>>(key,   Wk, bk, kp);
    gemm_bias_kernel<<<ggrid, 256>>>(value, Wv, bv, vp);

    attn_kernel<<<dim3(S_ / 64, B_ * H_), 256, ATTN_SMEM_BYTES>>>(mask);

    gemm_bias_kernel<<<ggrid, 256>>>(ap, Wo, bo, out);
}

// round 6
// speedup vs baseline: 1.3739x; 1.3739x over previous
#include <cuda_runtime.h>
#include <cstdint>

#define B_   4
#define S_   2048
#define EMB_ 1024
#define H_   16
#define D_   64
#define MROWS (B_ * S_)   // 8192

#define QS_STRIDE 65
#define KS_STRIDE 65
#define VS_STRIDE 64
#define ATTN_SMEM_FLOATS (64 * QS_STRIDE + 64 * KS_STRIDE + 64 * VS_STRIDE)
#define ATTN_SMEM_BYTES  (ATTN_SMEM_FLOATS * 4)

// Scratch (device-global arrays: allocation-free per harness rules)
__device__ float g_q[MROWS * EMB_];
__device__ float g_k[MROWS * EMB_];
__device__ float g_v[MROWS * EMB_];
__device__ float g_attn[MROWS * EMB_];
__device__ float g_wt[4][EMB_ * EMB_];   // transposed weights: Wt[n][k] = W[k][n]

// ---------------------------------------------------------------------------
// fp32 -> tf32 (round-to-nearest) as raw b32
// ---------------------------------------------------------------------------
__device__ __forceinline__ uint32_t f2tf32(float f) {
    uint32_t r;
    asm("cvt.rna.tf32.f32 %0, %1;" : "=r"(r) : "f"(f));
    return r;
}

// mma.sync m16n8k8 tf32: D(16x8,f32) += A(16x8,tf32 row) * B(8x8,tf32 col)
__device__ __forceinline__ void mma_tf32(float c[4], const uint32_t a[4],
                                         const uint32_t b[2]) {
    asm volatile(
        "mma.sync.aligned.m16n8k8.row.col.f32.tf32.tf32.f32 "
        "{%0,%1,%2,%3}, {%4,%5,%6,%7}, {%8,%9}, {%0,%1,%2,%3};"
        : "+f"(c[0]), "+f"(c[1]), "+f"(c[2]), "+f"(c[3])
        : "r"(a[0]), "r"(a[1]), "r"(a[2]), "r"(a[3]), "r"(b[0]), "r"(b[1]));
}

// ---------------------------------------------------------------------------
// 1024x1024 fp32 transpose (for weight matrices)
// ---------------------------------------------------------------------------
__global__ void transpose_k(const float* __restrict__ src, float* __restrict__ dst) {
    __shared__ float t[32][33];
    int x = blockIdx.x * 32 + threadIdx.x;
    int y = blockIdx.y * 32 + threadIdx.y;
    #pragma unroll
    for (int i = 0; i < 32; i += 8)
        t[threadIdx.y + i][threadIdx.x] = src[(size_t)(y + i) * EMB_ + x];
    __syncthreads();
    x = blockIdx.y * 32 + threadIdx.x;
    y = blockIdx.x * 32 + threadIdx.y;
    #pragma unroll
    for (int i = 0; i < 32; i += 8)
        dst[(size_t)(y + i) * EMB_ + x] = t[threadIdx.x][threadIdx.y + i];
}

// ---------------------------------------------------------------------------
// tf32 mma.sync GEMM: C[M,1024] = A[M,1024] @ Wt^T + bias
// (Wt[n][k] so that C[m][n] = sum_k A[m][k] * Wt[n][k].)
// Block: 128x128 tile, BK=32, 8 warps (4 M x 2 N), warp tile 32x64.
// Fragments per warp/kstep: 2 M-tiles(16) x 8 N-tiles(8), m16n8k8.
// ---------------------------------------------------------------------------
#define BKT     32
#define KTILES  (EMB_ / BKT)      // 32
#define TSTRIDE 36                // smem row stride in words (conflict-free frags)

__global__ void __launch_bounds__(256) gemm_mma_kernel(
    const float* __restrict__ A,
    const float* __restrict__ Wt,
    const float* __restrict__ bias,
    float* __restrict__ C)
{
    __shared__ uint32_t As[128 * TSTRIDE];   // tf32 bits, A[m][k]
    __shared__ uint32_t Bs[128 * TSTRIDE];   // tf32 bits, Wt[n][k]

    const int tid  = threadIdx.x;
    const int warp = tid >> 5;
    const int lane = tid & 31;
    const int g    = lane >> 2;      // group 0..7
    const int t    = lane & 3;       // thread-in-group 0..3
    const int wm   = warp >> 1;      // 0..3  -> 32-row slice
    const int wn   = warp & 1;       // 0..1  -> 64-col slice
    const int m0   = blockIdx.y * 128;
    const int n0   = blockIdx.x * 128;

    float acc[2][8][4];
    #pragma unroll
    for (int i = 0; i < 2; ++i)
        #pragma unroll
        for (int j = 0; j < 8; ++j)
            #pragma unroll
            for (int c = 0; c < 4; ++c) acc[i][j][c] = 0.f;

    const float* Ag = A  + (size_t)m0 * EMB_;
    const float* Bg = Wt + (size_t)n0 * EMB_;

    for (int kt = 0; kt < KTILES; ++kt) {
        const int kb = kt * BKT;
        // Stage A and B tiles (128 rows x 32 floats), converting fp32->tf32.
        #pragma unroll
        for (int it = 0; it < 4; ++it) {
            int f  = tid + it * 256;     // 0..1023
            int r  = f >> 3;             // 0..127
            int c4 = (f & 7) * 4;        // 0,4,...,28
            float4 va = *(const float4*)(Ag + (size_t)r * EMB_ + kb + c4);
            uint32_t* ap = &As[r * TSTRIDE + c4];
            ap[0] = f2tf32(va.x); ap[1] = f2tf32(va.y);
            ap[2] = f2tf32(va.z); ap[3] = f2tf32(va.w);
            float4 vb = *(const float4*)(Bg + (size_t)r * EMB_ + kb + c4);
            uint32_t* bp = &Bs[r * TSTRIDE + c4];
            bp[0] = f2tf32(vb.x); bp[1] = f2tf32(vb.y);
            bp[2] = f2tf32(vb.z); bp[3] = f2tf32(vb.w);
        }
        __syncthreads();

        #pragma unroll
        for (int ks = 0; ks < 4; ++ks) {
            const int k0 = ks * 8;
            uint32_t afr[2][4];
            #pragma unroll
            for (int mt = 0; mt < 2; ++mt) {
                int row = wm * 32 + mt * 16 + g;
                afr[mt][0] = As[row * TSTRIDE + k0 + t];
                afr[mt][1] = As[(row + 8) * TSTRIDE + k0 + t];
                afr[mt][2] = As[row * TSTRIDE + k0 + t + 4];
                afr[mt][3] = As[(row + 8) * TSTRIDE + k0 + t + 4];
            }
            uint32_t bfr[8][2];
            #pragma unroll
            for (int nt = 0; nt < 8; ++nt) {
                int col = wn * 64 + nt * 8 + g;
                bfr[nt][0] = Bs[col * TSTRIDE + k0 + t];
                bfr[nt][1] = Bs[col * TSTRIDE + k0 + t + 4];
            }
            #pragma unroll
            for (int mt = 0; mt < 2; ++mt)
                #pragma unroll
                for (int nt = 0; nt < 8; ++nt)
                    mma_tf32(acc[mt][nt], afr[mt], bfr[nt]);
        }
        __syncthreads();
    }

    // Epilogue: fragment -> global with bias. c0,c1: row g; c2,c3: row g+8.
    #pragma unroll
    for (int mt = 0; mt < 2; ++mt) {
        #pragma unroll
        for (int nt = 0; nt < 8; ++nt) {
            int n = n0 + wn * 64 + nt * 8 + 2 * t;
            float2 bv = *(const float2*)(bias + n);
            int r0 = m0 + wm * 32 + mt * 16 + g;
            float2 v0 = { acc[mt][nt][0] + bv.x, acc[mt][nt][1] + bv.y };
            *(float2*)(C + (size_t)r0 * EMB_ + n) = v0;
            float2 v1 = { acc[mt][nt][2] + bv.x, acc[mt][nt][3] + bv.y };
            *(float2*)(C + (size_t)(r0 + 8) * EMB_ + n) = v1;
        }
    }
}

// ---------------------------------------------------------------------------
// Flash attention (unchanged from passing round 4)
// ---------------------------------------------------------------------------
__global__ void __launch_bounds__(256) attn_kernel(const int* __restrict__ mask)
{
    extern __shared__ float smem[];
    float* Qs = smem;                                // [64][65]
    float* Ks = smem + 64 * QS_STRIDE;               // [64][65]; reused as P
    float* Vs = smem + 64 * (QS_STRIDE + KS_STRIDE); // [64][64]

    const int tid = threadIdx.x;
    const int tx  = tid & 15;
    const int ty  = tid >> 4;
    const int bh  = blockIdx.y;
    const int b   = bh >> 4;
    const int h   = bh & 15;
    const int q0  = blockIdx.x << 6;

    const float* qg = g_q + ((size_t)(b * S_ + q0)) * EMB_ + h * D_;
    #pragma unroll
    for (int it = 0; it < 4; ++it) {
        int r = (tid >> 4) + (it << 4);
        int c = (tid & 15) << 2;
        float4 t = *(const float4*)(qg + (size_t)r * EMB_ + c);
        Qs[r * QS_STRIDE + c + 0] = t.x;
        Qs[r * QS_STRIDE + c + 1] = t.y;
        Qs[r * QS_STRIDE + c + 2] = t.z;
        Qs[r * QS_STRIDE + c + 3] = t.w;
    }

    float O[4][4] = {};
    float m_i[4], l_i[4];
    #pragma unroll
    for (int i = 0; i < 4; ++i) { m_i[i] = -1e30f; l_i[i] = 0.f; }

    __syncthreads();

    const int* mrow = mask + b * S_;

    for (int kt = 0; kt < S_ / 64; ++kt) {
        const int k0 = kt << 6;
        const float* kg = g_k + ((size_t)(b * S_ + k0)) * EMB_ + h * D_;
        const float* vg = g_v + ((size_t)(b * S_ + k0)) * EMB_ + h * D_;

        #pragma unroll
        for (int it = 0; it < 4; ++it) {
            int r = (tid >> 4) + (it << 4);
            int c = (tid & 15) << 2;
            float4 tk = *(const float4*)(kg + (size_t)r * EMB_ + c);
            Ks[r * KS_STRIDE + c + 0] = tk.x;
            Ks[r * KS_STRIDE + c + 1] = tk.y;
            Ks[r * KS_STRIDE + c + 2] = tk.z;
            Ks[r * KS_STRIDE + c + 3] = tk.w;
            float4 tv = *(const float4*)(vg + (size_t)r * EMB_ + c);
            *(float4*)&Vs[r * VS_STRIDE + c] = tv;
        }
        __syncthreads();

        float S[4][4] = {};
        #pragma unroll 8
        for (int d = 0; d < 64; ++d) {
            float qa[4], kb[4];
            #pragma unroll
            for (int i = 0; i < 4; ++i) qa[i] = Qs[(ty * 4 + i) * QS_STRIDE + d];
            #pragma unroll
            for (int j = 0; j < 4; ++j) kb[j] = Ks[(tx * 4 + j) * KS_STRIDE + d];
            #pragma unroll
            for (int i = 0; i < 4; ++i)
                #pragma unroll
                for (int j = 0; j < 4; ++j)
                    S[i][j] = fmaf(qa[i], kb[j], S[i][j]);
        }

        int4 mv = *(const int4*)(mrow + k0 + tx * 4);
        float madd[4] = { mv.x ? 0.f : -1e30f, mv.y ? 0.f : -1e30f,
                          mv.z ? 0.f : -1e30f, mv.w ? 0.f : -1e30f };
        #pragma unroll
        for (int i = 0; i < 4; ++i)
            #pragma unroll
            for (int j = 0; j < 4; ++j)
                S[i][j] = S[i][j] * 0.125f + madd[j];

        float a_i[4];
        #pragma unroll
        for (int i = 0; i < 4; ++i) {
            float mx = fmaxf(fmaxf(S[i][0], S[i][1]), fmaxf(S[i][2], S[i][3]));
            #pragma unroll
            for (int off = 8; off; off >>= 1)
                mx = fmaxf(mx, __shfl_xor_sync(0xffffffffu, mx, off));
            float mn = fmaxf(m_i[i], mx);
            a_i[i] = __expf(m_i[i] - mn);
            m_i[i] = mn;
            float sum = 0.f;
            #pragma unroll
            for (int j = 0; j < 4; ++j) {
                S[i][j] = __expf(S[i][j] - mn);
                sum += S[i][j];
            }
            #pragma unroll
            for (int off = 8; off; off >>= 1)
                sum += __shfl_xor_sync(0xffffffffu, sum, off);
            l_i[i] = l_i[i] * a_i[i] + sum;
        }

        __syncthreads();
        #pragma unroll
        for (int i = 0; i < 4; ++i)
            #pragma unroll
            for (int j = 0; j < 4; ++j)
                Ks[(ty * 4 + i) * KS_STRIDE + tx * 4 + j] = S[i][j];
        __syncthreads();

        #pragma unroll
        for (int i = 0; i < 4; ++i)
            #pragma unroll
            for (int j = 0; j < 4; ++j)
                O[i][j] *= a_i[i];

        #pragma unroll 8
        for (int kk = 0; kk < 64; ++kk) {
            float pr[4], vr[4];
            #pragma unroll
            for (int i = 0; i < 4; ++i) pr[i] = Ks[(ty * 4 + i) * KS_STRIDE + kk];
            *(float4*)vr = *(const float4*)&Vs[kk * VS_STRIDE + tx * 4];
            #pragma unroll
            for (int i = 0; i < 4; ++i)
                #pragma unroll
                for (int j = 0; j < 4; ++j)
                    O[i][j] = fmaf(pr[i], vr[j], O[i][j]);
        }
        __syncthreads();
    }

    float* og = g_attn + ((size_t)(b * S_ + q0)) * EMB_ + h * D_;
    #pragma unroll
    for (int i = 0; i < 4; ++i) {
        float inv = 1.0f / l_i[i];
        float4 o = { O[i][0] * inv, O[i][1] * inv, O[i][2] * inv, O[i][3] * inv };
        *(float4*)(og + (size_t)(ty * 4 + i) * EMB_ + tx * 4) = o;
    }
}

// ===========================================================================
extern "C" void kernel_launch(void* const* d_in, const int* in_sizes, int n_in,
                              void* d_out, int out_size)
{
    const float* query = (const float*)d_in[0];
    const float* key   = (const float*)d_in[1];
    const float* value = (const float*)d_in[2];
    const int*   mask  = (const int*)d_in[3];
    const float* Wq = (const float*)d_in[4];
    const float* bq = (const float*)d_in[5];
    const float* Wk = (const float*)d_in[6];
    const float* bk = (const float*)d_in[7];
    const float* Wv = (const float*)d_in[8];
    const float* bv = (const float*)d_in[9];
    const float* Wo = (const float*)d_in[10];
    const float* bo = (const float*)d_in[11];
    float* out = (float*)d_out;

    float *qp, *kp, *vp, *ap, *wtp;
    cudaGetSymbolAddress((void**)&qp, g_q);
    cudaGetSymbolAddress((void**)&kp, g_k);
    cudaGetSymbolAddress((void**)&vp, g_v);
    cudaGetSymbolAddress((void**)&ap, g_attn);
    cudaGetSymbolAddress((void**)&wtp, g_wt);
    float* wtq = wtp;
    float* wtk = wtp + 1 * EMB_ * EMB_;
    float* wtv = wtp + 2 * EMB_ * EMB_;
    float* wto = wtp + 3 * EMB_ * EMB_;

    static int attr_set = 0;
    if (!attr_set) {
        cudaFuncSetAttribute(attn_kernel,
                             cudaFuncAttributeMaxDynamicSharedMemorySize,
                             ATTN_SMEM_BYTES);
        attr_set = 1;
    }

    // Transpose the 4 weight matrices (W[k][n] -> Wt[n][k])
    dim3 tgrid(EMB_ / 32, EMB_ / 32), tblk(32, 8);
    transpose_k<<<tgrid, tblk>>>(Wq, wtq);
    transpose_k<<<tgrid, tblk>>>(Wk, wtk);
    transpose_k<<<tgrid, tblk>>>(Wv, wtv);
    transpose_k<<<tgrid, tblk>>>(Wo, wto);

    dim3 ggrid(EMB_ / 128, MROWS / 128);   // (8, 64)
    gemm_mma_kernel<<<ggrid, 256>>>(query, wtq, bq, qp);
    gemm_mma_kernel<<<ggrid, 256>>>(key,   wtk, bk, kp);
    gemm_mma_kernel<<<ggrid, 256>>>(value, wtv, bv, vp);

    attn_kernel<<<dim3(S_ / 64, B_ * H_), 256, ATTN_SMEM_BYTES>>>(mask);

    gemm_mma_kernel<<<ggrid, 256>>>(ap, wto, bo, out);
}